// round 11
// baseline (speedup 1.0000x reference)
#include <cuda_runtime.h>
#include <math_constants.h>

// Reservoir2D: split-sim (2 CTAs/sample, global-memory halo exchange, no clusters)
// + co-scheduled threefry/erfinv noise producers with atomic work stealing.
// Grid 296 x 512 = 2 CTAs/SM, all co-resident.
//   CTAs [0,128): sim half-sample (16 rows x 32 cols, 1 thread/oscillator).
//   CTAs [128,296): noise producers (ILP-4 quads, stealing, quad-count chunks).

#define BATCHN 64
#define NN     1024
#define NSTEP  1000
#define NOUT   10
#define LENTB  20
#define FEATS  (NN * LENTB)
#define ETOT   (BATCHN * NN)          // 65536 per step
#define CHSTEP 10
#define NCHUNK (NSTEP / CHSTEP)       // 100
#define SIMC   128
#define NPROD  168
#define TOTAL_CTAS (SIMC + NPROD)     // 296 = 2*148
#define TPB    512
#define QPC    ((CHSTEP * ETOT) / 4)  // 163840 quads per chunk

__device__ float    g_noise[NSTEP * ETOT];   // 262 MB scratch
__device__ unsigned g_done[128];             // per-chunk produced-quad counters
__device__ unsigned g_work[128];             // per-chunk steal counters
__device__ float    g_halo[SIMC * 128];      // per sim CTA: [phase][2][32] floats
__device__ unsigned g_hflag[SIMC];           // per sim CTA: steps posted (monotonic)
__device__ float    g_partial[BATCHN * NOUT];// rank1 partial logits
__device__ unsigned g_rflag[BATCHN];         // rank1 partials ready

// ---- bit-exact division by small integer constant: q = fma(x,c1, x*c2) ----
__device__ __forceinline__ float divc(float x, float c1, float c2) {
    return fmaf(x, c1, x * c2);
}
#define DC(d) (float)(1.0/(d)), (float)(1.0/(d) - (double)(float)(1.0/(d)))

// ---------------- JAX threefry2x32 (exact) ----------------
__device__ __forceinline__ void tf2x32(unsigned k0, unsigned k1,
                                       unsigned x0, unsigned x1,
                                       unsigned& o0, unsigned& o1) {
    unsigned k2 = k0 ^ k1 ^ 0x1BD11BDAu;
    x0 += k0; x1 += k1;
#define TF_R(r) { x0 += x1; x1 = __funnelshift_l(x1, x1, (r)); x1 ^= x0; }
    TF_R(13) TF_R(15) TF_R(26) TF_R(6)
    x0 += k1; x1 += k2 + 1u;
    TF_R(17) TF_R(29) TF_R(16) TF_R(24)
    x0 += k2; x1 += k0 + 2u;
    TF_R(13) TF_R(15) TF_R(26) TF_R(6)
    x0 += k0; x1 += k1 + 3u;
    TF_R(17) TF_R(29) TF_R(16) TF_R(24)
    x0 += k1; x1 += k2 + 4u;
    TF_R(13) TF_R(15) TF_R(26) TF_R(6)
    x0 += k2; x1 += k0 + 5u;
#undef TF_R
    o0 = x0; o1 = x1;
}

// ---------------- XLA ErfInv32 (Giles polynomial, exact) ----------------
__device__ __forceinline__ float erfinv_xla(float x) {
    float w = -log1pf(-x * x);
    float p;
    if (w < 5.0f) {
        w = w - 2.5f;
        p = 2.81022636e-08f;
        p = fmaf(p, w, 3.43273939e-07f);
        p = fmaf(p, w, -3.5233877e-06f);
        p = fmaf(p, w, -4.39150654e-06f);
        p = fmaf(p, w, 0.00021858087f);
        p = fmaf(p, w, -0.00125372503f);
        p = fmaf(p, w, -0.00417768164f);
        p = fmaf(p, w, 0.246640727f);
        p = fmaf(p, w, 1.50140941f);
    } else {
        w = sqrtf(w) - 3.0f;
        p = -0.000200214257f;
        p = fmaf(p, w, 0.000100950558f);
        p = fmaf(p, w, 0.00134934322f);
        p = fmaf(p, w, -0.00367342844f);
        p = fmaf(p, w, 0.00573950773f);
        p = fmaf(p, w, -0.0076224613f);
        p = fmaf(p, w, 0.00943887047f);
        p = fmaf(p, w, 1.00167406f);
        p = fmaf(p, w, 2.83297682f);
    }
    return p * x;
}

__device__ __forceinline__ float bits_to_noise(unsigned bits) {
    const float U_LO   = -0.99999994039535522461f;
    const float SQRT2  = 1.41421353816986083984f;
    const float NSCALE = 0.001f * 3.1622776985168457f;
    float f = __uint_as_float((bits >> 9) | 0x3F800000u) - 1.0f;
    float u = fmaxf(f * 2.0f + U_LO, U_LO);
    return NSCALE * (SQRT2 * erfinv_xla(u));
}

// Quad of noise values for elements e0..e0+3, same step key.
__device__ __forceinline__ float4 noise_quad(unsigned k0, unsigned k1, unsigned e0) {
    unsigned k2 = k0 ^ k1 ^ 0x1BD11BDAu;
    unsigned a0 = k0, a1 = e0 + k1;
    unsigned b0 = k0, b1 = (e0 + 1u) + k1;
    unsigned c0 = k0, c1 = (e0 + 2u) + k1;
    unsigned d0 = k0, d1 = (e0 + 3u) + k1;
#define R4(r) { a0 += a1; b0 += b1; c0 += c1; d0 += d1; \
                a1 = __funnelshift_l(a1, a1, (r)); b1 = __funnelshift_l(b1, b1, (r)); \
                c1 = __funnelshift_l(c1, c1, (r)); d1 = __funnelshift_l(d1, d1, (r)); \
                a1 ^= a0; b1 ^= b0; c1 ^= c0; d1 ^= d0; }
#define INJ4(kx, ky, cnt) { unsigned kyc = (ky) + (cnt); \
                a0 += (kx); b0 += (kx); c0 += (kx); d0 += (kx); \
                a1 += kyc;  b1 += kyc;  c1 += kyc;  d1 += kyc; }
    R4(13) R4(15) R4(26) R4(6)  INJ4(k1, k2, 1u)
    R4(17) R4(29) R4(16) R4(24) INJ4(k2, k0, 2u)
    R4(13) R4(15) R4(26) R4(6)  INJ4(k0, k1, 3u)
    R4(17) R4(29) R4(16) R4(24) INJ4(k1, k2, 4u)
    R4(13) R4(15) R4(26) R4(6)  INJ4(k2, k0, 5u)
#undef R4
#undef INJ4
    float4 r;
    r.x = bits_to_noise(a0 ^ a1);
    r.y = bits_to_noise(b0 ^ b1);
    r.z = bits_to_noise(c0 ^ c1);
    r.w = bits_to_noise(d0 ^ d1);
    return r;
}

__device__ __forceinline__ unsigned ld_acq(const unsigned* p) {
    unsigned v;
    asm volatile("ld.acquire.gpu.global.b32 %0, [%1];" : "=r"(v) : "l"(p));
    return v;
}
__device__ __forceinline__ void st_rel(unsigned* p, unsigned v) {
    asm volatile("st.release.gpu.global.b32 [%0], %1;" :: "l"(p), "r"(v) : "memory");
}

__global__ void reset_cnt_kernel() {
    if (threadIdx.x < 128) { g_done[threadIdx.x] = 0u; g_work[threadIdx.x] = 0u; }
    if (threadIdx.x < SIMC)   g_hflag[threadIdx.x] = 0u;
    if (threadIdx.x < BATCHN) g_rflag[threadIdx.x] = 0u;
}

__global__ __launch_bounds__(TPB, 2)
void Reservoir2D_kernel(const float* __restrict__ xin,
                        const float* __restrict__ W,
                        const float* __restrict__ bias,
                        float* __restrict__ out) {
    __shared__ float Tsh[2][16 * 32];   // sim: own 16 rows, double-buffered
    __shared__ float red[16 * NOUT];    // sim partial logits per warp
    __shared__ uint2 keys[NSTEP];       // producer only
    __shared__ unsigned sh_base;        // producer only

    const int n = threadIdx.x;
    const int b = blockIdx.x;

    if (b >= SIMC) {
        // ============ NOISE PRODUCER (work-stealing, quads) ============
        for (int t = n; t < NSTEP; t += TPB) {
            unsigned o0, o1;
            tf2x32(0u, 1u, 0u, (unsigned)t, o0, o1);   // fold-like split of key(1)
            keys[t] = make_uint2(o0, o1);
        }
        __syncthreads();

        float4* __restrict__ g4 = reinterpret_cast<float4*>(g_noise);
        for (int c = 0; c < NCHUNK; ++c) {
            for (;;) {
                if (n == 0) sh_base = atomicAdd(&g_work[c], (unsigned)TPB);
                __syncthreads();
                unsigned base = sh_base;
                __syncthreads();
                if (base >= (unsigned)QPC) break;
                unsigned qi = base + (unsigned)n;
                if (qi < (unsigned)QPC) {
                    int gq = c * QPC + (int)qi;
                    int t  = gq >> 14;                      // 16384 quads per step
                    unsigned e0 = (unsigned)((gq << 2) & (ETOT - 1));
                    uint2 kk = keys[t];
                    g4[gq] = noise_quad(kk.x, kk.y, e0);
                }
                __syncthreads();
                if (n == 0) {
                    unsigned cnt = min((unsigned)TPB, (unsigned)QPC - base);
                    __threadfence();
                    atomicAdd(&g_done[c], cnt);
                }
            }
        }
        return;
    }

    // =============== SIMULATION: half-sample per CTA ===============
    const int s    = b >> 1;
    const int rank = b & 1;
    const int ri = n >> 5;              // local row 0..15 (warp == row)
    const int j  = n & 31;
    const int gi = rank * 16 + ri;      // sample row 0..31
    const int jm = (j + 31) & 31;
    const int jp = (j + 1)  & 31;
    const int e  = s * NN + gi * 32 + j;
    const bool topw = (ri == 0);
    const bool botw = (ri == 15);
    const bool bw   = topw || botw;

    // halo buffers: mine (write) and peer's (read)
    float* __restrict__ haloW = g_halo + (size_t)b * 128;            // [phase][2][32]
    const float* __restrict__ haloR = g_halo + (size_t)(b ^ 1) * 128;
    unsigned* myflag   = &g_hflag[b];
    unsigned* peerflag = &g_hflag[b ^ 1];
    const int wslot = topw ? 0 : 32;    // my row0 -> slot0, row15 -> slot1
    // read: xm (row above) for topw = peer slot1; xp (row below) for botw = peer slot0
    const int rslot = topw ? 32 : 0;

    const float Vd = 11.0f + 2.0f * xin[e];
    float v = 0.0f;
    float T = 325.0f;
    float prevI = CUDART_INF_F;
    int   cd = 0;
    unsigned mask = 0;
    unsigned binbit = 1u;
    int c50 = 50;
    const float LOG_R_INS = 4.6051702499389648f;   // f32(log(100))

    if (n == 0) { while (ld_acq(&g_done[0]) < (unsigned)QPC) __nanosleep(64); }
    __syncthreads();
    const float* __restrict__ nzp = g_noise + e;
    float nz = __ldg(nzp);
    nzp += ETOT;

    int p = 0;
    for (int t = 0; t < NSTEP; ++t) {
        Tsh[p][ri * 32 + j] = T;
        if (bw) haloW[(t & 1) * 64 + wslot + j] = T;   // post my boundary row
        __syncthreads();
        if (n == 0) { __threadfence(); st_rel(myflag, (unsigned)(t + 1)); }

        const int tn = t + 1;
        if (tn < NSTEP && (tn % CHSTEP) == 0) {
            const int c = tn / CHSTEP;
            if (n == 0) { while (ld_acq(&g_done[c]) < (unsigned)QPC) __nanosleep(64); }
            __syncthreads();
        }
        float nz_next = (tn < NSTEP) ? __ldg(nzp) : 0.0f;
        nzp += ETOT;

        // ---- front half of model (independent of Laplacian) ----
        float xs = divc(T - 340.0f, DC(5.0));
        float sg = 1.0f / (1.0f + expf(-xs));
        float a  = (1.0f - sg) * LOG_R_INS;
        float G  = expf(-a);
        float I  = v * G;
        float vn = v + divc(10.0f * (divc(Vd - v, DC(12.0)) - I), DC(100.0));

        // rising-edge peak detection (needs only I)
        bool pk = (I > 1.5f) && (prevI <= 1.5f) && (cd <= 0);
        if (pk) { mask |= binbit; cd = 101; }
        else    { cd -= 1; }
        if (--c50 == 0) { c50 = 50; binbit <<= 1; }

        // ---- neighbors ----
        const float* Ts = Tsh[p];
        float ym = Ts[ri * 32 + jm];
        float yp = Ts[ri * 32 + jp];
        float xm, xp;
        if (bw) {
            while (ld_acq(peerflag) < (unsigned)(t + 1)) { }
            float h = __ldg(&haloR[(t & 1) * 64 + rslot + j]);
            if (topw) { xm = h;                     xp = Ts[(ri + 1) * 32 + j]; }
            else      { xm = Ts[(ri - 1) * 32 + j]; xp = h; }
        } else {
            xm = Ts[(ri - 1) * 32 + j];
            xp = Ts[(ri + 1) * 32 + j];
        }
        float lap = ((xm + xp) + ym) + yp - 4.0f * T;

        float q  = (v * I - (T - 325.0f)) + 0.02f * lap;
        float Tn = (T + divc(10.0f * q, DC(1000.0))) + nz;

        prevI = I; v = vn; T = Tn;
        nz = nz_next; p ^= 1;
    }

    // ---- readout: partial logits over this CTA's 512 oscillators ----
    float acc[NOUT];
#pragma unroll
    for (int o = 0; o < NOUT; ++o) acc[o] = 0.0f;
    const int f0 = (gi * 32 + j) * LENTB;
#pragma unroll
    for (int tb = 0; tb < LENTB; ++tb) {
        if ((mask >> tb) & 1u) {
            const float* wp = W + (f0 + tb);
#pragma unroll
            for (int o = 0; o < NOUT; ++o) acc[o] += wp[o * FEATS];
        }
    }
#pragma unroll
    for (int o = 0; o < NOUT; ++o) {
        float a2 = acc[o];
#pragma unroll
        for (int sft = 16; sft > 0; sft >>= 1)
            a2 += __shfl_xor_sync(0xFFFFFFFFu, a2, sft);
        acc[o] = a2;
    }
    const int wid = n >> 5;
    if ((n & 31) == 0) {
#pragma unroll
        for (int o = 0; o < NOUT; ++o) red[wid * NOUT + o] = acc[o];
    }
    __syncthreads();

    if (n == 0) {
        float lg[NOUT];
#pragma unroll
        for (int o = 0; o < NOUT; ++o) {
            float sacc = 0.0f;
            for (int w = 0; w < 16; ++w) sacc += red[w * NOUT + o];
            lg[o] = sacc;
        }
        if (rank == 1) {
#pragma unroll
            for (int o = 0; o < NOUT; ++o) g_partial[s * NOUT + o] = lg[o];
            __threadfence();
            st_rel(&g_rflag[s], 1u);
        } else {
            while (ld_acq(&g_rflag[s]) == 0u) { }
#pragma unroll
            for (int o = 0; o < NOUT; ++o)
                lg[o] = (bias[o] + lg[o]) + __ldg(&g_partial[s * NOUT + o]);
            float m = lg[0];
#pragma unroll
            for (int o = 1; o < NOUT; ++o) m = fmaxf(m, lg[o]);
            float se = 0.0f;
#pragma unroll
            for (int o = 0; o < NOUT; ++o) se += expf(lg[o] - m);
            float lse = logf(se);
#pragma unroll
            for (int o = 0; o < NOUT; ++o) out[s * NOUT + o] = (lg[o] - m) - lse;
        }
    }
}

extern "C" void kernel_launch(void* const* d_in, const int* in_sizes, int n_in,
                              void* d_out, int out_size) {
    const float* x    = (const float*)d_in[0];
    const float* W    = (const float*)d_in[1];
    const float* bias = (const float*)d_in[2];
    float* out = (float*)d_out;
    reset_cnt_kernel<<<1, 256>>>();
    Reservoir2D_kernel<<<TOTAL_CTAS, TPB>>>(x, W, bias, out);
}

// round 12
// speedup vs baseline: 6.7068x; 6.7068x over previous
#include <cuda_runtime.h>
#include <math_constants.h>

// Reservoir2D: R7 topology (proven) + 2^23-entry noise lookup table.
// Grid 296 x 512 = 2 CTAs/SM, all co-resident.
//   CTAs [0,64): sim, 1 thread = 2 adjacent oscillators (ILP-2, bit-exact).
//   CTAs [64,296): noise producers: threefry bits -> 32MB table lookup.
// Prelude kernel builds table[pattern] = NSCALE*(sqrt2*erfinv(u(pattern)))
// once per replay (identical fp ops -> bit-exact).

#define BATCHN 64
#define NN     1024
#define NSTEP  1000
#define NOUT   10
#define LENTB  20
#define FEATS  (NN * LENTB)
#define ETOT   (BATCHN * NN)        // 65536 per step
#define CHSTEP 10
#define NCHUNK (NSTEP / CHSTEP)     // 100
#define NPROD  232
#define TOTAL_CTAS (BATCHN + NPROD) // 296 = 2*148
#define TPB    512
#define TBLN   (1u << 23)           // 8388608 entries, 32 MB

__device__ float    g_noise[NSTEP * ETOT];   // 262 MB scratch
__device__ float    g_tbl[TBLN];             // 32 MB noise table
__device__ unsigned g_cnt[128];              // per-chunk completion counters
__device__ unsigned g_work[128];             // per-chunk steal counters

// ---- bit-exact division by small integer constant: q = fma(x,c1, x*c2) ----
__device__ __forceinline__ float divc(float x, float c1, float c2) {
    return fmaf(x, c1, x * c2);
}
#define DC(d) (float)(1.0/(d)), (float)(1.0/(d) - (double)(float)(1.0/(d)))

// ---------------- JAX threefry2x32 (exact) ----------------
__device__ __forceinline__ void tf2x32(unsigned k0, unsigned k1,
                                       unsigned x0, unsigned x1,
                                       unsigned& o0, unsigned& o1) {
    unsigned k2 = k0 ^ k1 ^ 0x1BD11BDAu;
    x0 += k0; x1 += k1;
#define TF_R(r) { x0 += x1; x1 = __funnelshift_l(x1, x1, (r)); x1 ^= x0; }
    TF_R(13) TF_R(15) TF_R(26) TF_R(6)
    x0 += k1; x1 += k2 + 1u;
    TF_R(17) TF_R(29) TF_R(16) TF_R(24)
    x0 += k2; x1 += k0 + 2u;
    TF_R(13) TF_R(15) TF_R(26) TF_R(6)
    x0 += k0; x1 += k1 + 3u;
    TF_R(17) TF_R(29) TF_R(16) TF_R(24)
    x0 += k1; x1 += k2 + 4u;
    TF_R(13) TF_R(15) TF_R(26) TF_R(6)
    x0 += k2; x1 += k0 + 5u;
#undef TF_R
    o0 = x0; o1 = x1;
}

// ---------------- XLA ErfInv32 (Giles polynomial, exact) ----------------
__device__ __forceinline__ float erfinv_xla(float x) {
    float w = -log1pf(-x * x);
    float p;
    if (w < 5.0f) {
        w = w - 2.5f;
        p = 2.81022636e-08f;
        p = fmaf(p, w, 3.43273939e-07f);
        p = fmaf(p, w, -3.5233877e-06f);
        p = fmaf(p, w, -4.39150654e-06f);
        p = fmaf(p, w, 0.00021858087f);
        p = fmaf(p, w, -0.00125372503f);
        p = fmaf(p, w, -0.00417768164f);
        p = fmaf(p, w, 0.246640727f);
        p = fmaf(p, w, 1.50140941f);
    } else {
        w = sqrtf(w) - 3.0f;
        p = -0.000200214257f;
        p = fmaf(p, w, 0.000100950558f);
        p = fmaf(p, w, 0.00134934322f);
        p = fmaf(p, w, -0.00367342844f);
        p = fmaf(p, w, 0.00573950773f);
        p = fmaf(p, w, -0.0076224613f);
        p = fmaf(p, w, 0.00943887047f);
        p = fmaf(p, w, 1.00167406f);
        p = fmaf(p, w, 2.83297682f);
    }
    return p * x;
}

// Threefry bits for elements e0..e0+3 (same key), ILP-4.
__device__ __forceinline__ uint4 tf_quad_bits(unsigned k0, unsigned k1, unsigned e0) {
    unsigned k2 = k0 ^ k1 ^ 0x1BD11BDAu;
    unsigned a0 = k0, a1 = e0 + k1;
    unsigned b0 = k0, b1 = (e0 + 1u) + k1;
    unsigned c0 = k0, c1 = (e0 + 2u) + k1;
    unsigned d0 = k0, d1 = (e0 + 3u) + k1;
#define R4(r) { a0 += a1; b0 += b1; c0 += c1; d0 += d1; \
                a1 = __funnelshift_l(a1, a1, (r)); b1 = __funnelshift_l(b1, b1, (r)); \
                c1 = __funnelshift_l(c1, c1, (r)); d1 = __funnelshift_l(d1, d1, (r)); \
                a1 ^= a0; b1 ^= b0; c1 ^= c0; d1 ^= d0; }
#define INJ4(kx, ky, cnt) { unsigned kyc = (ky) + (cnt); \
                a0 += (kx); b0 += (kx); c0 += (kx); d0 += (kx); \
                a1 += kyc;  b1 += kyc;  c1 += kyc;  d1 += kyc; }
    R4(13) R4(15) R4(26) R4(6)  INJ4(k1, k2, 1u)
    R4(17) R4(29) R4(16) R4(24) INJ4(k2, k0, 2u)
    R4(13) R4(15) R4(26) R4(6)  INJ4(k0, k1, 3u)
    R4(17) R4(29) R4(16) R4(24) INJ4(k1, k2, 4u)
    R4(13) R4(15) R4(26) R4(6)  INJ4(k2, k0, 5u)
#undef R4
#undef INJ4
    return make_uint4(a0 ^ a1, b0 ^ b1, c0 ^ c1, d0 ^ d1);
}

__device__ __forceinline__ unsigned ld_acq(const unsigned* p) {
    unsigned v;
    asm volatile("ld.acquire.gpu.global.b32 %0, [%1];" : "=r"(v) : "l"(p));
    return v;
}

__global__ void reset_cnt_kernel() {
    if (threadIdx.x < 128) { g_cnt[threadIdx.x] = 0u; g_work[threadIdx.x] = 0u; }
}

// Build noise table: tbl[pat] = NSCALE*(SQRT2*erfinv(max(f(pat)*2+U_LO, U_LO)))
__global__ __launch_bounds__(TPB)
void build_tbl_kernel() {
    const float U_LO   = -0.99999994039535522461f;
    const float SQRT2  = 1.41421353816986083984f;
    const float NSCALE = 0.001f * 3.1622776985168457f;
    unsigned idx = blockIdx.x * TPB + threadIdx.x;
    const unsigned stride = gridDim.x * TPB;
    for (; idx < TBLN; idx += stride) {
        float f = __uint_as_float(idx | 0x3F800000u) - 1.0f;
        float u = fmaxf(f * 2.0f + U_LO, U_LO);
        g_tbl[idx] = NSCALE * (SQRT2 * erfinv_xla(u));
    }
}

__global__ __launch_bounds__(TPB, 2)
void Reservoir2D_kernel(const float* __restrict__ xin,
                        const float* __restrict__ W,
                        const float* __restrict__ bias,
                        float* __restrict__ out) {
    __shared__ float Tsh[2][NN];        // sim only
    __shared__ float red[16 * NOUT];    // sim only
    __shared__ uint2 keys[NSTEP];       // producer only
    __shared__ unsigned sh_base;        // producer only

    const int n = threadIdx.x;
    const int b = blockIdx.x;

    if (b >= BATCHN) {
        // ====== NOISE PRODUCER (work-stealing; table lookup) ======
        for (int t = n; t < NSTEP; t += TPB) {
            unsigned o0, o1;
            tf2x32(0u, 1u, 0u, (unsigned)t, o0, o1);   // fold-like split of key(1)
            keys[t] = make_uint2(o0, o1);
        }
        __syncthreads();

        const unsigned quadsPerChunk = (CHSTEP * ETOT) / 4;   // 163840
        float4* __restrict__ g4 = reinterpret_cast<float4*>(g_noise);
        for (int c = 0; c < NCHUNK; ++c) {
            for (;;) {
                if (n == 0) sh_base = atomicAdd(&g_work[c], (unsigned)TPB);
                __syncthreads();
                unsigned base = sh_base;
                __syncthreads();
                if (base >= quadsPerChunk) break;
                unsigned qi = base + (unsigned)n;
                if (qi < quadsPerChunk) {
                    int gq = c * (int)quadsPerChunk + (int)qi;
                    int t  = gq >> 14;                      // 16384 quads per step
                    unsigned e0 = (unsigned)((gq << 2) & (ETOT - 1));
                    uint2 kk = keys[t];
                    uint4 bb = tf_quad_bits(kk.x, kk.y, e0);
                    float4 r;
                    r.x = __ldg(&g_tbl[bb.x >> 9]);
                    r.y = __ldg(&g_tbl[bb.y >> 9]);
                    r.z = __ldg(&g_tbl[bb.z >> 9]);
                    r.w = __ldg(&g_tbl[bb.w >> 9]);
                    g4[gq] = r;
                }
            }
            if (n == 0) {
                __threadfence();
                atomicAdd(&g_cnt[c], 1u);
            }
        }
        return;
    }

    // ===================== SIMULATION (ILP-2) =====================
    // thread n handles oscillators (i, jj) and (i, jj+1), jj even.
    const int i  = n >> 4;
    const int jj = (n & 15) << 1;
    const int rowm = (((i + 31) & 31) << 5);
    const int rowp = (((i + 1)  & 31) << 5);
    const int rowi = (i << 5);
    const int jm1 = (jj + 31) & 31;
    const int jp2 = (jj + 2)  & 31;
    const int e   = b * NN + rowi + jj;      // even -> float2-aligned

    const float Vd0 = 11.0f + 2.0f * xin[e];
    const float Vd1 = 11.0f + 2.0f * xin[e + 1];
    float v0 = 0.0f, v1 = 0.0f;
    float T0 = 325.0f, T1 = 325.0f;
    float pI0 = CUDART_INF_F, pI1 = CUDART_INF_F;
    int   cd0 = 0, cd1 = 0;
    unsigned m0 = 0, m1 = 0;
    unsigned binbit = 1u;
    int c50 = 50;

    const float LOG_R_INS = 4.6051702499389648f;   // f32(log(100))

    if (n == 0) { while (ld_acq(&g_cnt[0]) < NPROD) __nanosleep(64); }
    __syncthreads();
    const float2* __restrict__ nzp = reinterpret_cast<const float2*>(g_noise + e);
    float2 nz = __ldg(nzp);
    nzp += ETOT / 2;

    int p = 0;
    for (int t = 0; t < NSTEP; ++t) {
        *reinterpret_cast<float2*>(&Tsh[p][rowi + jj]) = make_float2(T0, T1);

        const int tn = t + 1;
        if (tn < NSTEP && (tn % CHSTEP) == 0) {
            const int c = tn / CHSTEP;
            if (n == 0) { while (ld_acq(&g_cnt[c]) < NPROD) __nanosleep(64); }
            __syncthreads();
        }
        float2 nz_next = make_float2(0.0f, 0.0f);
        if (tn < NSTEP) nz_next = __ldg(nzp);
        nzp += ETOT / 2;

        __syncthreads();
        const float* Ts = Tsh[p];
        float2 up = *reinterpret_cast<const float2*>(&Ts[rowm + jj]);
        float2 dn = *reinterpret_cast<const float2*>(&Ts[rowp + jj]);
        float  lf = Ts[rowi + jm1];
        float  rt = Ts[rowi + jp2];
        // exact ref order: ((xm + xp) + ym) + yp - 4T
        float lap0 = ((up.x + dn.x) + lf) + T1 - 4.0f * T0;
        float lap1 = ((up.y + dn.y) + T0) + rt - 4.0f * T1;

        // ---- device model x2 (bit-identical; constant divides via 2-FMA) ----
        float xs0 = divc(T0 - 340.0f, DC(5.0));
        float xs1 = divc(T1 - 340.0f, DC(5.0));
        float s0  = 1.0f / (1.0f + expf(-xs0));
        float s1  = 1.0f / (1.0f + expf(-xs1));
        float G0  = expf(-((1.0f - s0) * LOG_R_INS));
        float G1  = expf(-((1.0f - s1) * LOG_R_INS));
        float I0  = v0 * G0;
        float I1  = v1 * G1;

        float vn0 = v0 + divc(10.0f * (divc(Vd0 - v0, DC(12.0)) - I0), DC(100.0));
        float vn1 = v1 + divc(10.0f * (divc(Vd1 - v1, DC(12.0)) - I1), DC(100.0));
        float q0  = (v0 * I0 - (T0 - 325.0f)) + 0.02f * lap0;
        float q1  = (v1 * I1 - (T1 - 325.0f)) + 0.02f * lap1;
        float Tn0 = (T0 + divc(10.0f * q0, DC(1000.0))) + nz.x;
        float Tn1 = (T1 + divc(10.0f * q1, DC(1000.0))) + nz.y;

        // ---- rising-edge peak detection, refractory 101 ----
        bool pk0 = (I0 > 1.5f) && (pI0 <= 1.5f) && (cd0 <= 0);
        bool pk1 = (I1 > 1.5f) && (pI1 <= 1.5f) && (cd1 <= 0);
        if (pk0) { m0 |= binbit; cd0 = 101; } else { cd0 -= 1; }
        if (pk1) { m1 |= binbit; cd1 = 101; } else { cd1 -= 1; }
        if (--c50 == 0) { c50 = 50; binbit <<= 1; }

        pI0 = I0; pI1 = I1; v0 = vn0; v1 = vn1; T0 = Tn0; T1 = Tn1;
        nz = nz_next; p ^= 1;
    }

    // ---- readout ----
    float acc[NOUT];
#pragma unroll
    for (int o = 0; o < NOUT; ++o) acc[o] = 0.0f;
    const int f0 = (rowi + jj) * LENTB;
#pragma unroll
    for (int tb = 0; tb < LENTB; ++tb) {
        if ((m0 >> tb) & 1u) {
            const float* wp = W + (f0 + tb);
#pragma unroll
            for (int o = 0; o < NOUT; ++o) acc[o] += wp[o * FEATS];
        }
        if ((m1 >> tb) & 1u) {
            const float* wp = W + (f0 + LENTB + tb);
#pragma unroll
            for (int o = 0; o < NOUT; ++o) acc[o] += wp[o * FEATS];
        }
    }
#pragma unroll
    for (int o = 0; o < NOUT; ++o) {
        float a2 = acc[o];
#pragma unroll
        for (int sft = 16; sft > 0; sft >>= 1)
            a2 += __shfl_xor_sync(0xFFFFFFFFu, a2, sft);
        acc[o] = a2;
    }
    const int wid = n >> 5;
    if ((n & 31) == 0) {
#pragma unroll
        for (int o = 0; o < NOUT; ++o) red[wid * NOUT + o] = acc[o];
    }
    __syncthreads();

    if (n == 0) {
        float lg[NOUT];
#pragma unroll
        for (int o = 0; o < NOUT; ++o) {
            float sacc = bias[o];
            for (int w = 0; w < 16; ++w) sacc += red[w * NOUT + o];
            lg[o] = sacc;
        }
        float m = lg[0];
#pragma unroll
        for (int o = 1; o < NOUT; ++o) m = fmaxf(m, lg[o]);
        float se = 0.0f;
#pragma unroll
        for (int o = 0; o < NOUT; ++o) se += expf(lg[o] - m);
        float lse = logf(se);
#pragma unroll
        for (int o = 0; o < NOUT; ++o) out[b * NOUT + o] = (lg[o] - m) - lse;
    }
}

extern "C" void kernel_launch(void* const* d_in, const int* in_sizes, int n_in,
                              void* d_out, int out_size) {
    const float* x    = (const float*)d_in[0];
    const float* W    = (const float*)d_in[1];
    const float* bias = (const float*)d_in[2];
    float* out = (float*)d_out;
    reset_cnt_kernel<<<1, 128>>>();
    build_tbl_kernel<<<1024, TPB>>>();
    Reservoir2D_kernel<<<TOTAL_CTAS, TPB>>>(x, W, bias, out);
}

// round 13
// speedup vs baseline: 8.9961x; 1.3413x over previous
#include <cuda_runtime.h>
#include <math_constants.h>

// Reservoir2D: R7 topology + producer batch x4 + CHSTEP 20.
// Grid 296 x 512 = 2 CTAs/SM, all co-resident.
//   CTAs [0,64): sim, 1 thread = 2 adjacent oscillators (ILP-2, bit-exact).
//   CTAs [64,296): threefry/erfinv noise producers, work stealing in
//                  2048-quad batches (4 sequential quads per thread).

#define BATCHN 64
#define NN     1024
#define NSTEP  1000
#define NOUT   10
#define LENTB  20
#define FEATS  (NN * LENTB)
#define ETOT   (BATCHN * NN)        // 65536 per step
#define CHSTEP 20
#define NCHUNK (NSTEP / CHSTEP)     // 50
#define NPROD  232
#define TOTAL_CTAS (BATCHN + NPROD) // 296 = 2*148
#define TPB    512
#define QPC    ((CHSTEP * ETOT) / 4)  // 327680 quads per chunk
#define BATCHQ (TPB * 4)              // 2048 quads per steal-grab

__device__ float    g_noise[NSTEP * ETOT];   // 262 MB scratch
__device__ unsigned g_cnt[128];              // per-chunk completion counters
__device__ unsigned g_work[128];             // per-chunk steal counters

// ---- bit-exact division by small integer constant: q = fma(x,c1, x*c2) ----
__device__ __forceinline__ float divc(float x, float c1, float c2) {
    return fmaf(x, c1, x * c2);
}
#define DC(d) (float)(1.0/(d)), (float)(1.0/(d) - (double)(float)(1.0/(d)))

// ---------------- JAX threefry2x32 (exact) ----------------
__device__ __forceinline__ void tf2x32(unsigned k0, unsigned k1,
                                       unsigned x0, unsigned x1,
                                       unsigned& o0, unsigned& o1) {
    unsigned k2 = k0 ^ k1 ^ 0x1BD11BDAu;
    x0 += k0; x1 += k1;
#define TF_R(r) { x0 += x1; x1 = __funnelshift_l(x1, x1, (r)); x1 ^= x0; }
    TF_R(13) TF_R(15) TF_R(26) TF_R(6)
    x0 += k1; x1 += k2 + 1u;
    TF_R(17) TF_R(29) TF_R(16) TF_R(24)
    x0 += k2; x1 += k0 + 2u;
    TF_R(13) TF_R(15) TF_R(26) TF_R(6)
    x0 += k0; x1 += k1 + 3u;
    TF_R(17) TF_R(29) TF_R(16) TF_R(24)
    x0 += k1; x1 += k2 + 4u;
    TF_R(13) TF_R(15) TF_R(26) TF_R(6)
    x0 += k2; x1 += k0 + 5u;
#undef TF_R
    o0 = x0; o1 = x1;
}

// ---------------- XLA ErfInv32 (Giles polynomial, exact) ----------------
__device__ __forceinline__ float erfinv_xla(float x) {
    float w = -log1pf(-x * x);
    float p;
    if (w < 5.0f) {
        w = w - 2.5f;
        p = 2.81022636e-08f;
        p = fmaf(p, w, 3.43273939e-07f);
        p = fmaf(p, w, -3.5233877e-06f);
        p = fmaf(p, w, -4.39150654e-06f);
        p = fmaf(p, w, 0.00021858087f);
        p = fmaf(p, w, -0.00125372503f);
        p = fmaf(p, w, -0.00417768164f);
        p = fmaf(p, w, 0.246640727f);
        p = fmaf(p, w, 1.50140941f);
    } else {
        w = sqrtf(w) - 3.0f;
        p = -0.000200214257f;
        p = fmaf(p, w, 0.000100950558f);
        p = fmaf(p, w, 0.00134934322f);
        p = fmaf(p, w, -0.00367342844f);
        p = fmaf(p, w, 0.00573950773f);
        p = fmaf(p, w, -0.0076224613f);
        p = fmaf(p, w, 0.00943887047f);
        p = fmaf(p, w, 1.00167406f);
        p = fmaf(p, w, 2.83297682f);
    }
    return p * x;
}

__device__ __forceinline__ float bits_to_noise(unsigned bits) {
    const float U_LO   = -0.99999994039535522461f;
    const float SQRT2  = 1.41421353816986083984f;
    const float NSCALE = 0.001f * 3.1622776985168457f;
    float f = __uint_as_float((bits >> 9) | 0x3F800000u) - 1.0f;
    float u = fmaxf(f * 2.0f + U_LO, U_LO);
    return NSCALE * (SQRT2 * erfinv_xla(u));
}

// Quad of noise values for elements e0..e0+3, same step key.
__device__ __forceinline__ float4 noise_quad(unsigned k0, unsigned k1, unsigned e0) {
    unsigned k2 = k0 ^ k1 ^ 0x1BD11BDAu;
    unsigned a0 = k0, a1 = e0 + k1;
    unsigned b0 = k0, b1 = (e0 + 1u) + k1;
    unsigned c0 = k0, c1 = (e0 + 2u) + k1;
    unsigned d0 = k0, d1 = (e0 + 3u) + k1;
#define R4(r) { a0 += a1; b0 += b1; c0 += c1; d0 += d1; \
                a1 = __funnelshift_l(a1, a1, (r)); b1 = __funnelshift_l(b1, b1, (r)); \
                c1 = __funnelshift_l(c1, c1, (r)); d1 = __funnelshift_l(d1, d1, (r)); \
                a1 ^= a0; b1 ^= b0; c1 ^= c0; d1 ^= d0; }
#define INJ4(kx, ky, cnt) { unsigned kyc = (ky) + (cnt); \
                a0 += (kx); b0 += (kx); c0 += (kx); d0 += (kx); \
                a1 += kyc;  b1 += kyc;  c1 += kyc;  d1 += kyc; }
    R4(13) R4(15) R4(26) R4(6)  INJ4(k1, k2, 1u)
    R4(17) R4(29) R4(16) R4(24) INJ4(k2, k0, 2u)
    R4(13) R4(15) R4(26) R4(6)  INJ4(k0, k1, 3u)
    R4(17) R4(29) R4(16) R4(24) INJ4(k1, k2, 4u)
    R4(13) R4(15) R4(26) R4(6)  INJ4(k2, k0, 5u)
#undef R4
#undef INJ4
    float4 r;
    r.x = bits_to_noise(a0 ^ a1);
    r.y = bits_to_noise(b0 ^ b1);
    r.z = bits_to_noise(c0 ^ c1);
    r.w = bits_to_noise(d0 ^ d1);
    return r;
}

__device__ __forceinline__ unsigned ld_acq(const unsigned* p) {
    unsigned v;
    asm volatile("ld.acquire.gpu.global.b32 %0, [%1];" : "=r"(v) : "l"(p));
    return v;
}

__global__ void reset_cnt_kernel() {
    if (threadIdx.x < 128) { g_cnt[threadIdx.x] = 0u; g_work[threadIdx.x] = 0u; }
}

__global__ __launch_bounds__(TPB, 2)
void Reservoir2D_kernel(const float* __restrict__ xin,
                        const float* __restrict__ W,
                        const float* __restrict__ bias,
                        float* __restrict__ out) {
    __shared__ float Tsh[2][NN];        // sim only
    __shared__ float red[16 * NOUT];    // sim only
    __shared__ uint2 keys[NSTEP];       // producer only
    __shared__ unsigned sh_base;        // producer only

    const int n = threadIdx.x;
    const int b = blockIdx.x;

    if (b >= BATCHN) {
        // ====== NOISE PRODUCER (work-stealing, 2048-quad batches) ======
        for (int t = n; t < NSTEP; t += TPB) {
            unsigned o0, o1;
            tf2x32(0u, 1u, 0u, (unsigned)t, o0, o1);   // fold-like split of key(1)
            keys[t] = make_uint2(o0, o1);
        }
        __syncthreads();

        float4* __restrict__ g4 = reinterpret_cast<float4*>(g_noise);
        for (int c = 0; c < NCHUNK; ++c) {
            const int qbase = c * QPC;
            for (;;) {
                if (n == 0) sh_base = atomicAdd(&g_work[c], (unsigned)BATCHQ);
                __syncthreads();
                unsigned base = sh_base;
                __syncthreads();
                if (base >= (unsigned)QPC) break;
#pragma unroll
                for (int r = 0; r < 4; ++r) {
                    unsigned qi = base + (unsigned)(r * TPB + n);
                    if (qi < (unsigned)QPC) {
                        int gq = qbase + (int)qi;
                        int t  = gq >> 14;                  // 16384 quads per step
                        unsigned e0 = (unsigned)((gq << 2) & (ETOT - 1));
                        uint2 kk = keys[t];
                        g4[gq] = noise_quad(kk.x, kk.y, e0);
                    }
                }
            }
            if (n == 0) {
                __threadfence();
                atomicAdd(&g_cnt[c], 1u);
            }
        }
        return;
    }

    // ===================== SIMULATION (ILP-2) =====================
    // thread n handles oscillators (i, jj) and (i, jj+1), jj even.
    const int i  = n >> 4;
    const int jj = (n & 15) << 1;
    const int rowm = (((i + 31) & 31) << 5);
    const int rowp = (((i + 1)  & 31) << 5);
    const int rowi = (i << 5);
    const int jm1 = (jj + 31) & 31;
    const int jp2 = (jj + 2)  & 31;
    const int e   = b * NN + rowi + jj;      // even -> float2-aligned

    const float Vd0 = 11.0f + 2.0f * xin[e];
    const float Vd1 = 11.0f + 2.0f * xin[e + 1];
    float v0 = 0.0f, v1 = 0.0f;
    float T0 = 325.0f, T1 = 325.0f;
    float pI0 = CUDART_INF_F, pI1 = CUDART_INF_F;
    int   cd0 = 0, cd1 = 0;
    unsigned m0 = 0, m1 = 0;
    unsigned binbit = 1u;
    int c50 = 50;

    const float LOG_R_INS = 4.6051702499389648f;   // f32(log(100))

    if (n == 0) { while (ld_acq(&g_cnt[0]) < NPROD) __nanosleep(64); }
    __syncthreads();
    const float2* __restrict__ nzp = reinterpret_cast<const float2*>(g_noise + e);
    float2 nz = __ldg(nzp);
    nzp += ETOT / 2;

    int p = 0;
    for (int t = 0; t < NSTEP; ++t) {
        *reinterpret_cast<float2*>(&Tsh[p][rowi + jj]) = make_float2(T0, T1);

        const int tn = t + 1;
        if (tn < NSTEP && (tn % CHSTEP) == 0) {
            const int c = tn / CHSTEP;
            if (n == 0) { while (ld_acq(&g_cnt[c]) < NPROD) __nanosleep(64); }
            __syncthreads();
        }
        float2 nz_next = make_float2(0.0f, 0.0f);
        if (tn < NSTEP) nz_next = __ldg(nzp);
        nzp += ETOT / 2;

        __syncthreads();
        const float* Ts = Tsh[p];
        float2 up = *reinterpret_cast<const float2*>(&Ts[rowm + jj]);
        float2 dn = *reinterpret_cast<const float2*>(&Ts[rowp + jj]);
        float  lf = Ts[rowi + jm1];
        float  rt = Ts[rowi + jp2];
        // exact ref order: ((xm + xp) + ym) + yp - 4T
        float lap0 = ((up.x + dn.x) + lf) + T1 - 4.0f * T0;
        float lap1 = ((up.y + dn.y) + T0) + rt - 4.0f * T1;

        // ---- device model x2 (bit-identical; constant divides via 2-FMA) ----
        float xs0 = divc(T0 - 340.0f, DC(5.0));
        float xs1 = divc(T1 - 340.0f, DC(5.0));
        float s0  = 1.0f / (1.0f + expf(-xs0));
        float s1  = 1.0f / (1.0f + expf(-xs1));
        float G0  = expf(-((1.0f - s0) * LOG_R_INS));
        float G1  = expf(-((1.0f - s1) * LOG_R_INS));
        float I0  = v0 * G0;
        float I1  = v1 * G1;

        float vn0 = v0 + divc(10.0f * (divc(Vd0 - v0, DC(12.0)) - I0), DC(100.0));
        float vn1 = v1 + divc(10.0f * (divc(Vd1 - v1, DC(12.0)) - I1), DC(100.0));
        float q0  = (v0 * I0 - (T0 - 325.0f)) + 0.02f * lap0;
        float q1  = (v1 * I1 - (T1 - 325.0f)) + 0.02f * lap1;
        float Tn0 = (T0 + divc(10.0f * q0, DC(1000.0))) + nz.x;
        float Tn1 = (T1 + divc(10.0f * q1, DC(1000.0))) + nz.y;

        // ---- rising-edge peak detection, refractory 101 ----
        bool pk0 = (I0 > 1.5f) && (pI0 <= 1.5f) && (cd0 <= 0);
        bool pk1 = (I1 > 1.5f) && (pI1 <= 1.5f) && (cd1 <= 0);
        if (pk0) { m0 |= binbit; cd0 = 101; } else { cd0 -= 1; }
        if (pk1) { m1 |= binbit; cd1 = 101; } else { cd1 -= 1; }
        if (--c50 == 0) { c50 = 50; binbit <<= 1; }

        pI0 = I0; pI1 = I1; v0 = vn0; v1 = vn1; T0 = Tn0; T1 = Tn1;
        nz = nz_next; p ^= 1;
    }

    // ---- readout ----
    float acc[NOUT];
#pragma unroll
    for (int o = 0; o < NOUT; ++o) acc[o] = 0.0f;
    const int f0 = (rowi + jj) * LENTB;
#pragma unroll
    for (int tb = 0; tb < LENTB; ++tb) {
        if ((m0 >> tb) & 1u) {
            const float* wp = W + (f0 + tb);
#pragma unroll
            for (int o = 0; o < NOUT; ++o) acc[o] += wp[o * FEATS];
        }
        if ((m1 >> tb) & 1u) {
            const float* wp = W + (f0 + LENTB + tb);
#pragma unroll
            for (int o = 0; o < NOUT; ++o) acc[o] += wp[o * FEATS];
        }
    }
#pragma unroll
    for (int o = 0; o < NOUT; ++o) {
        float a2 = acc[o];
#pragma unroll
        for (int sft = 16; sft > 0; sft >>= 1)
            a2 += __shfl_xor_sync(0xFFFFFFFFu, a2, sft);
        acc[o] = a2;
    }
    const int wid = n >> 5;
    if ((n & 31) == 0) {
#pragma unroll
        for (int o = 0; o < NOUT; ++o) red[wid * NOUT + o] = acc[o];
    }
    __syncthreads();

    if (n == 0) {
        float lg[NOUT];
#pragma unroll
        for (int o = 0; o < NOUT; ++o) {
            float sacc = bias[o];
            for (int w = 0; w < 16; ++w) sacc += red[w * NOUT + o];
            lg[o] = sacc;
        }
        float m = lg[0];
#pragma unroll
        for (int o = 1; o < NOUT; ++o) m = fmaxf(m, lg[o]);
        float se = 0.0f;
#pragma unroll
        for (int o = 0; o < NOUT; ++o) se += expf(lg[o] - m);
        float lse = logf(se);
#pragma unroll
        for (int o = 0; o < NOUT; ++o) out[b * NOUT + o] = (lg[o] - m) - lse;
    }
}

extern "C" void kernel_launch(void* const* d_in, const int* in_sizes, int n_in,
                              void* d_out, int out_size) {
    const float* x    = (const float*)d_in[0];
    const float* W    = (const float*)d_in[1];
    const float* bias = (const float*)d_in[2];
    float* out = (float*)d_out;
    reset_cnt_kernel<<<1, 128>>>();
    Reservoir2D_kernel<<<TOTAL_CTAS, TPB>>>(x, W, bias, out);
}